// round 12
// baseline (speedup 1.0000x reference)
#include <cuda_runtime.h>
#include <cuda_fp16.h>
#include <cstdint>

// PatchEmbed round 12: R11 + the missing __syncthreads() after the one-time
// smem wb1 init (race introduced in R10, exposed by R11's scheduling change).
// ldmatrix.x4 A-fragments + double-buffered pipeline in both GEMM mainloops.
// Numerics: fp16 m16n8k16, f32 accumulate (same as R10, rel_err 3.55e-4).

constexpr int Bb = 8, Nn = 16384, Mc = 2048, Kn = 32;
constexpr int C1 = 64, C2 = 128, C3 = 256;
constexpr int P  = 8;                        // points/group -> M = 256 rows
constexpr int NGRP = Bb * Mc / P;            // 2048
constexpr int GRID = 152;
constexpr int THREADS = 256;
constexpr int MROWS = P * Kn;                // 256

constexpr int S1W = 36;                      // h1 row stride in 32-bit words
constexpr int S2W = 68;                      // h2 row stride in words
constexpr int S1B = S1W * 4;                 // 144 B
constexpr int S2B = S2W * 4;                 // 272 B
constexpr int H1W = MROWS * S1W;
constexpr int H2W = MROWS * S2W;
constexpr uint32_t SMEM_BYTES = (H1W + H2W) * 4;   // 106496 B

__device__ __forceinline__ uint32_t packh2(float lo, float hi) {
    __half2 h = __floats2half2_rn(lo, hi);
    return *reinterpret_cast<uint32_t*>(&h);
}

__device__ __forceinline__ uint32_t smem_u32(const void* p) {
    uint32_t a;
    asm("{ .reg .u64 t; cvta.to.shared.u64 t, %1; cvt.u32.u64 %0, t; }" : "=r"(a) : "l"(p));
    return a;
}

__device__ __forceinline__ void ldsm4(uint4& v, uint32_t addr) {
    asm volatile("ldmatrix.sync.aligned.m8n8.x4.shared.b16 {%0,%1,%2,%3}, [%4];"
                 : "=r"(v.x), "=r"(v.y), "=r"(v.z), "=r"(v.w) : "r"(addr));
}

__device__ __forceinline__ void mma16(float& d0, float& d1, float& d2, float& d3,
                                      uint32_t a0, uint32_t a1, uint32_t a2, uint32_t a3,
                                      uint32_t b0, uint32_t b1) {
    asm volatile(
        "mma.sync.aligned.m16n8k16.row.col.f32.f16.f16.f32 "
        "{%0,%1,%2,%3},{%4,%5,%6,%7},{%8,%9},{%0,%1,%2,%3};"
        : "+f"(d0), "+f"(d1), "+f"(d2), "+f"(d3)
        : "r"(a0), "r"(a1), "r"(a2), "r"(a3), "r"(b0), "r"(b1));
}

__global__ __launch_bounds__(THREADS, 1)
void pe_mma(const float* __restrict__ xyz,
            const float* __restrict__ centers,
            const int*   __restrict__ idx,
            const float* __restrict__ W1, const float* __restrict__ b1,
            const float* __restrict__ W2, const float* __restrict__ b2,
            const float* __restrict__ W3, const float* __restrict__ b3,
            float* __restrict__ out) {
    extern __shared__ uint32_t smw[];
    uint32_t* h1u = smw;                     // [256][S1W] f16x2
    uint32_t* h2u = smw + H1W;               // [256][S2W]

    __shared__ float4 wb1[64];               // {w0,w1,w2,bias}

    const int tid  = threadIdx.x;
    const int warp = tid >> 5;
    const int lane = tid & 31;
    const int g    = lane >> 2;
    const int t    = lane & 3;

    const uint32_t h1a = smem_u32(h1u);
    const uint32_t h2a = smem_u32(h2u);
    const uint32_t lm1 = h1a + (uint32_t)(lane & 15) * S1B + (uint32_t)(lane >> 4) * 16;
    const uint32_t lm2 = h2a + (uint32_t)(lane & 15) * S2B + (uint32_t)(lane >> 4) * 16;

    // ---- one-time: W1/b1 table ----
    if (tid < 64)
        wb1[tid] = make_float4(__ldg(&W1[tid * 3 + 0]), __ldg(&W1[tid * 3 + 1]),
                               __ldg(&W1[tid * 3 + 2]), __ldg(&b1[tid]));

    // ---- one-time: resident f16 weight B-fragments ----
    const int c2b = warp * 16;
    uint32_t b2f[4][2][2];
#pragma unroll
    for (int kc = 0; kc < 4; kc++)
#pragma unroll
        for (int n = 0; n < 2; n++) {
            const int row = c2b + n * 8 + g;
            const float* wr = W2 + (size_t)row * C1 + kc * 16;
            b2f[kc][n][0] = packh2(__ldg(wr + 2 * t),     __ldg(wr + 2 * t + 1));
            b2f[kc][n][1] = packh2(__ldg(wr + 2 * t + 8), __ldg(wr + 2 * t + 9));
        }
    const int chb = warp * 32;
    uint32_t b3f[8][4][2];
#pragma unroll
    for (int kc = 0; kc < 8; kc++)
#pragma unroll
        for (int n = 0; n < 4; n++) {
            const int row = chb + n * 8 + g;
            const float* wr = W3 + (size_t)row * C2 + kc * 16;
            b3f[kc][n][0] = packh2(__ldg(wr + 2 * t),     __ldg(wr + 2 * t + 1));
            b3f[kc][n][1] = packh2(__ldg(wr + 2 * t + 8), __ldg(wr + 2 * t + 9));
        }
    float bias2[2][2];
#pragma unroll
    for (int n = 0; n < 2; n++) {
        bias2[n][0] = __ldg(&b2[c2b + n * 8 + 2 * t]);
        bias2[n][1] = __ldg(&b2[c2b + n * 8 + 2 * t + 1]);
    }

    __syncthreads();   // wb1 visible to ALL warps before any layer1 (R11 bug fix)

    auto gather = [&](int grp, float& lx, float& ly, float& lz) {
        const int bm0 = grp * P;
        const int b   = bm0 >> 11;
        const int bm  = bm0 + (tid >> 5);
        const int id  = __ldg(&idx[(size_t)bm * Kn + (tid & 31)]);
        const float* xp = xyz + ((size_t)b * Nn + id) * 3;
        const float* cp = centers + (size_t)bm * 3;
        lx = __ldg(xp + 0) - __ldg(cp + 0);
        ly = __ldg(xp + 1) - __ldg(cp + 1);
        lz = __ldg(xp + 2) - __ldg(cp + 2);
    };
    auto layer1 = [&](float lx, float ly, float lz) {
        uint32_t* ph = h1u + tid * S1W;
#pragma unroll
        for (int j4 = 0; j4 < 8; j4++) {
            uint4 o;
#pragma unroll
            for (int w = 0; w < 4; w++) {
                const int c0 = j4 * 8 + 2 * w;
                const float4 wa = wb1[c0];
                const float4 wb = wb1[c0 + 1];
                const float vlo = fmaxf(fmaf(wa.x, lx, fmaf(wa.y, ly, fmaf(wa.z, lz, wa.w))), 0.f);
                const float vhi = fmaxf(fmaf(wb.x, lx, fmaf(wb.y, ly, fmaf(wb.z, lz, wb.w))), 0.f);
                (&o.x)[w] = packh2(vlo, vhi);
            }
            *reinterpret_cast<uint4*>(ph + j4 * 4) = o;
        }
    };

    // ---- prologue ----
    int grp = blockIdx.x;
    if (grp < NGRP) {
        float lx, ly, lz;
        gather(grp, lx, ly, lz);
        layer1(lx, ly, lz);
    }
    __syncthreads();

    // ---- persistent group loop ----
    for (; grp < NGRP; grp += GRID) {
        const int bm0 = grp * P;

        float nlx, nly, nlz;
        {
            int gn = grp + GRID;
            if (gn >= NGRP) gn = NGRP - 1;
            gather(gn, nlx, nly, nlz);
        }

        // -- GEMM2: 4 passes of M=64; 16 pipelined (mt,kc) steps each --
#pragma unroll 1
        for (int pass = 0; pass < 4; pass++) {
            const uint32_t base = lm1 + (uint32_t)(pass * 64) * S1B;
            float acc[4][2][4];
#pragma unroll
            for (int mt = 0; mt < 4; mt++)
#pragma unroll
                for (int n = 0; n < 2; n++)
#pragma unroll
                    for (int i = 0; i < 4; i++) acc[mt][n][i] = 0.f;

            uint4 fr[2];
            ldsm4(fr[0], base);
#pragma unroll
            for (int s = 0; s < 16; s++) {
                const int mt = s >> 2, kc = s & 3;
                if (s + 1 < 16) {
                    const int s1 = s + 1;
                    ldsm4(fr[s1 & 1], base + (uint32_t)((s1 >> 2) * 16 * S1B + (s1 & 3) * 32));
                }
                const uint4 a = fr[s & 1];
#pragma unroll
                for (int n = 0; n < 2; n++)
                    mma16(acc[mt][n][0], acc[mt][n][1], acc[mt][n][2], acc[mt][n][3],
                          a.x, a.y, a.z, a.w, b2f[kc][n][0], b2f[kc][n][1]);
            }
            // epi2: +bias, relu, pack, store
#pragma unroll
            for (int mt = 0; mt < 4; mt++) {
                const int r0 = pass * 64 + mt * 16 + g;
#pragma unroll
                for (int n = 0; n < 2; n++) {
                    const int wcol = warp * 8 + n * 4 + t;
                    h2u[r0 * S2W + wcol] =
                        packh2(fmaxf(acc[mt][n][0] + bias2[n][0], 0.f),
                               fmaxf(acc[mt][n][1] + bias2[n][1], 0.f));
                    h2u[(r0 + 8) * S2W + wcol] =
                        packh2(fmaxf(acc[mt][n][2] + bias2[n][0], 0.f),
                               fmaxf(acc[mt][n][3] + bias2[n][1], 0.f));
                }
            }
        }
        __syncthreads();

        // -- GEMM3 + max epilogue: per p, 16 pipelined (hmt,kc) steps --
#pragma unroll 1
        for (int p = 0; p < P; p++) {
            const uint32_t base = lm2 + (uint32_t)(p * 32) * S2B;
            float acc[2][4][4];
#pragma unroll
            for (int h = 0; h < 2; h++)
#pragma unroll
                for (int n = 0; n < 4; n++)
#pragma unroll
                    for (int i = 0; i < 4; i++) acc[h][n][i] = 0.f;

            uint4 fr[2];
            ldsm4(fr[0], base);
#pragma unroll
            for (int s = 0; s < 16; s++) {
                const int hmt = s >> 3, kc = s & 7;
                if (s + 1 < 16) {
                    const int s1 = s + 1;
                    ldsm4(fr[s1 & 1], base + (uint32_t)((s1 >> 3) * 16 * S2B + (s1 & 7) * 32));
                }
                const uint4 a = fr[s & 1];
#pragma unroll
                for (int n = 0; n < 4; n++)
                    mma16(acc[hmt][n][0], acc[hmt][n][1], acc[hmt][n][2], acc[hmt][n][3],
                          a.x, a.y, a.z, a.w, b3f[kc][n][0], b3f[kc][n][1]);
            }

#pragma unroll
            for (int n = 0; n < 4; n++) {
                float ve = fmaxf(fmaxf(acc[0][n][0], acc[0][n][2]),
                                 fmaxf(acc[1][n][0], acc[1][n][2]));
                float vo = fmaxf(fmaxf(acc[0][n][1], acc[0][n][3]),
                                 fmaxf(acc[1][n][1], acc[1][n][3]));
#pragma unroll
                for (int s = 4; s < 32; s <<= 1) {
                    ve = fmaxf(ve, __shfl_xor_sync(0xffffffffu, ve, s));
                    vo = fmaxf(vo, __shfl_xor_sync(0xffffffffu, vo, s));
                }
                if (lane < 4) {
                    const int ch = chb + n * 8 + 2 * lane;
                    float2 o = {ve + __ldg(&b3[ch]), vo + __ldg(&b3[ch + 1])};
                    *reinterpret_cast<float2*>(out + (size_t)(bm0 + p) * C3 + ch) = o;
                }
            }
        }

        // -- layer1 for next group --
        layer1(nlx, nly, nlz);
        __syncthreads();
    }
}

extern "C" void kernel_launch(void* const* d_in, const int* in_sizes, int n_in,
                              void* d_out, int out_size) {
    (void)in_sizes; (void)n_in; (void)out_size;
    const float* xyz     = (const float*)d_in[0];
    const float* centers = (const float*)d_in[1];
    const int*   idx     = (const int*)  d_in[2];
    const float* W1      = (const float*)d_in[3];
    const float* b1      = (const float*)d_in[4];
    const float* W2      = (const float*)d_in[5];
    const float* b2      = (const float*)d_in[6];
    const float* W3      = (const float*)d_in[7];
    const float* b3      = (const float*)d_in[8];
    float*       out     = (float*)d_out;

    cudaFuncSetAttribute(pe_mma, cudaFuncAttributeMaxDynamicSharedMemorySize, SMEM_BYTES);
    pe_mma<<<GRID, THREADS, SMEM_BYTES>>>(xyz, centers, idx,
                                          W1, b1, W2, b2, W3, b3, out);
}